// round 1
// baseline (speedup 1.0000x reference)
#include <cuda_runtime.h>

#define PNUM   512
#define BATCH  256
#define LPREDS 2

__global__ void zero_out_kernel(float* o) { *o = 0.0f; }

__global__ __launch_bounds__(PNUM, 3)
void poly_match_kernel(const float* __restrict__ pred,
                       const float* __restrict__ gt,
                       float* __restrict__ out) {
    // sp: pred for this (l,b).  sg: gt doubled so (i+j)%512 is a linear walk.
    __shared__ float2 sp[PNUM];
    __shared__ float2 sg[2 * PNUM];
    __shared__ float  wmin[PNUM / 32];

    const int t  = threadIdx.x;          // shift index i
    const int lb = blockIdx.x;           // 0 .. L*B-1
    const int b  = lb & (BATCH - 1);

    const float2* predv = (const float2*)(pred + (size_t)lb * PNUM * 2);
    const float2* gtv   = (const float2*)(gt   + (size_t)b  * PNUM * 2);

    sp[t] = predv[t];
    float2 g = gtv[t];
    sg[t]        = g;
    sg[t + PNUM] = g;
    __syncthreads();

    float accx = 0.0f, accy = 0.0f;
    const float2* gp = sg + t;

    #pragma unroll 8
    for (int j = 0; j < PNUM; ++j) {
        float2 p = sp[j];      // uniform across warp -> LDS broadcast
        float2 q = gp[j];      // stride-8B across lanes -> conflict-free LDS.64
        float dx = p.x - q.x;
        float dy = p.y - q.y;
        float ax = fabsf(dx);
        float ay = fabsf(dy);
        float ux = fminf(ax, 1.0f);
        float uy = fminf(ay, 1.0f);
        // smoothL1(d) = u * (|d| - 0.5*u),  u = min(|d|, 1)
        accx = fmaf(ux, fmaf(-0.5f, ux, ax), accx);
        accy = fmaf(uy, fmaf(-0.5f, uy, ay), accy);
    }
    float v = accx + accy;     // = sum_j [sl1x + sl1y] for shift i = t

    // warp-level min
    #pragma unroll
    for (int off = 16; off; off >>= 1)
        v = fminf(v, __shfl_xor_sync(0xffffffffu, v, off));
    if ((t & 31) == 0) wmin[t >> 5] = v;
    __syncthreads();

    if (t < 16) {
        v = wmin[t];
        #pragma unroll
        for (int off = 8; off; off >>= 1)
            v = fminf(v, __shfl_xor_sync(0x0000ffffu, v, off));
        if (t == 0) {
            // contribution: min * (1/P) [mean_j] * (1/B) [mean_b] * (1/L)
            atomicAdd(out, v * (1.0f / ((float)PNUM * BATCH * LPREDS)));
        }
    }
}

extern "C" void kernel_launch(void* const* d_in, const int* in_sizes, int n_in,
                              void* d_out, int out_size) {
    const float* pred = (const float*)d_in[0];   // (L, B, P, 2) fp32
    const float* gt   = (const float*)d_in[1];   // (B, P, 2) fp32
    float* out = (float*)d_out;

    zero_out_kernel<<<1, 1>>>(out);
    poly_match_kernel<<<LPREDS * BATCH, PNUM>>>(pred, gt, out);
}

// round 2
// speedup vs baseline: 1.1130x; 1.1130x over previous
#include <cuda_runtime.h>

#define PNUM   512
#define BATCH  256
#define LPREDS 2
#define NLB    (LPREDS * BATCH)

__device__ unsigned g_min[NLB];

typedef unsigned long long u64;

__device__ __forceinline__ u64 pack2(float lo, float hi) {
    u64 r; asm("mov.b64 %0, {%1, %2};" : "=l"(r) : "f"(lo), "f"(hi)); return r;
}
__device__ __forceinline__ void unpack2(u64 v, float& lo, float& hi) {
    asm("mov.b64 {%0, %1}, %2;" : "=f"(lo), "=f"(hi) : "l"(v));
}
__device__ __forceinline__ u64 add2(u64 a, u64 b) {
    u64 d; asm("add.rn.f32x2 %0, %1, %2;" : "=l"(d) : "l"(a), "l"(b)); return d;
}
__device__ __forceinline__ u64 fma2(u64 a, u64 b, u64 c) {
    u64 d; asm("fma.rn.f32x2 %0, %1, %2, %3;" : "=l"(d) : "l"(a), "l"(b), "l"(c)); return d;
}

// smoothL1(p - q) summed into packed acc.  qn = -q (pre-negated in smem).
// smoothL1(d) = u*(|d| - 0.5u), u = min(|d|,1)
__device__ __forceinline__ void sl1_step(u64 p, u64 qn, u64 neghalf, u64& acc) {
    u64 d = add2(p, qn);
    float dlo, dhi; unpack2(d, dlo, dhi);
    float alo = __uint_as_float(__float_as_uint(dlo) & 0x7fffffffu);
    float ahi = __uint_as_float(__float_as_uint(dhi) & 0x7fffffffu);
    float ulo = fminf(alo, 1.0f);
    float uhi = fminf(ahi, 1.0f);
    u64 a2 = pack2(alo, ahi);
    u64 u2 = pack2(ulo, uhi);
    u64 w2 = fma2(u2, neghalf, a2);   // |d| - 0.5u
    acc     = fma2(u2, w2, acc);      // acc += u*(|d| - 0.5u)
}

__global__ void init_kernel() {
    g_min[threadIdx.x] = 0x7f800000u;  // +inf
}

__global__ __launch_bounds__(256, 8)
void poly_main(const float* __restrict__ pred, const float* __restrict__ gt) {
    // s_g : negated gt, doubled (1024 float2) -> linear walk, no mod
    // s_p : pred (512 float2)
    // s_ps: pred shifted by one (ps[k] = p[(k+1)%512]) for odd-shift warps' alignment
    __shared__ float4 s_g[512];
    __shared__ float4 s_p[256];
    __shared__ float4 s_ps[256];
    __shared__ float  wm[8];

    const int t    = threadIdx.x;
    const int lb   = blockIdx.x & (NLB - 1);
    const int half = blockIdx.x >> 9;            // 0 or 1 -> shift range half
    const int b    = lb & (BATCH - 1);

    const float2* pv = (const float2*)(pred + (size_t)lb * PNUM * 2);
    const float2* gv = (const float2*)(gt   + (size_t)b  * PNUM * 2);

    float2* g2  = (float2*)s_g;
    float2* p2  = (float2*)s_p;
    float2* ps2 = (float2*)s_ps;

    #pragma unroll
    for (int k = t; k < PNUM; k += 256) {
        float2 g = gv[k];
        float2 ng = make_float2(-g.x, -g.y);
        g2[k]        = ng;
        g2[k + PNUM] = ng;
        float2 p = pv[k];
        p2[k] = p;
        ps2[(k + PNUM - 1) & (PNUM - 1)] = p;   // ps2[k] = p[k+1]
    }
    __syncthreads();

    // warps 0-3: even shifts, warps 4-7: odd shifts (uniform parity per warp)
    const int i = (t < 128) ? (half * 256 + 2 * t)
                            : (half * 256 + 2 * (t - 128) + 1);

    // q float4 base: sg + i (even) or sg + i + 1 (odd) -> always 16B aligned
    const ulonglong2* qb = (const ulonglong2*)(g2 + i + (i & 1));
    // p float4 base: normal copy for even shifts (j=0,1,...), shifted for odd (j=1,2,...)
    const ulonglong2* pb = (i & 1) ? (const ulonglong2*)s_ps : (const ulonglong2*)s_p;

    const u64 NH = pack2(-0.5f, -0.5f);
    u64 acc0 = 0ull, acc1 = 0ull;   // packed {0,0}

    #pragma unroll 2
    for (int m = 0; m < PNUM / 2; ++m) {
        ulonglong2 P = pb[m];
        ulonglong2 Q = qb[m];
        sl1_step(P.x, Q.x, NH, acc0);
        sl1_step(P.y, Q.y, NH, acc1);
    }

    float a0, a1, a2, a3;
    unpack2(acc0, a0, a1);
    unpack2(acc1, a2, a3);
    float v = (a0 + a1) + (a2 + a3);   // dis sum for shift i (pre-division)

    #pragma unroll
    for (int o = 16; o; o >>= 1)
        v = fminf(v, __shfl_xor_sync(0xffffffffu, v, o));
    if ((t & 31) == 0) wm[t >> 5] = v;
    __syncthreads();

    if (t < 8) {
        v = wm[t];
        #pragma unroll
        for (int o = 4; o; o >>= 1)
            v = fminf(v, __shfl_xor_sync(0x000000ffu, v, o));
        if (t == 0)
            atomicMin(&g_min[lb], __float_as_uint(v));   // v >= 0: bit order == value order
    }
}

__global__ void finish_kernel(float* __restrict__ out) {
    __shared__ float wm[16];
    const int t = threadIdx.x;
    float v = __uint_as_float(g_min[t]);
    #pragma unroll
    for (int o = 16; o; o >>= 1)
        v += __shfl_xor_sync(0xffffffffu, v, o);
    if ((t & 31) == 0) wm[t >> 5] = v;
    __syncthreads();
    if (t < 16) {
        v = wm[t];
        #pragma unroll
        for (int o = 8; o; o >>= 1)
            v += __shfl_xor_sync(0x0000ffffu, v, o);
        if (t == 0)
            *out = v * (1.0f / ((float)PNUM * BATCH * LPREDS));
    }
}

extern "C" void kernel_launch(void* const* d_in, const int* in_sizes, int n_in,
                              void* d_out, int out_size) {
    const float* pred = (const float*)d_in[0];   // (L, B, P, 2) fp32
    const float* gt   = (const float*)d_in[1];   // (B, P, 2) fp32
    float* out = (float*)d_out;

    init_kernel<<<1, NLB>>>();
    poly_main<<<2 * NLB, 256>>>(pred, gt);
    finish_kernel<<<1, NLB>>>(out);
}

// round 3
// speedup vs baseline: 1.9180x; 1.7234x over previous
#include <cuda_runtime.h>
#include <cuda_fp16.h>

#define PNUM   512
#define BATCH  256
#define LPREDS 2
#define NLB    (LPREDS * BATCH)

__device__ float g_part[2 * NLB];   // per-block partial mins (written every run)

// smoothL1 on both components at once: d=p-q; u=min(|d|,1); acc += u*(|d|-0.5u)
__device__ __forceinline__ void sl1_h2(const unsigned pu, const unsigned qu,
                                       const __half2 one2, const __half2 nh2,
                                       __half2& acc) {
    __half2 p = *reinterpret_cast<const __half2*>(&pu);
    __half2 q = *reinterpret_cast<const __half2*>(&qu);
    __half2 d = __hsub2(p, q);
    __half2 a = __habs2(d);
    __half2 u = __hmin2(a, one2);
    __half2 w = __hfma2(u, nh2, a);      // |d| - 0.5u
    acc       = __hfma2(u, w, acc);      // += u*(|d| - 0.5u)
}

__global__ __launch_bounds__(128, 7)
void poly_main(const float* __restrict__ pred, const float* __restrict__ gt) {
    // point-packed fp16: one half2 per point (x,y)
    __shared__ __align__(16) __half2 sg[2 * PNUM];     // gt doubled (cyclic)
    __shared__ __align__(16) __half2 sp[4][PNUM];      // pred rotated by s=0..3
    __shared__ float wm[4];

    const int t   = threadIdx.x;
    const int bid = blockIdx.x;
    const int lb  = bid & (NLB - 1);
    const int h   = bid >> 9;              // which half of the 512 shifts
    const int b   = lb & (BATCH - 1);

    const float2* pv = (const float2*)(pred + (size_t)lb * PNUM * 2);
    const float2* gv = (const float2*)(gt   + (size_t)b  * PNUM * 2);

    #pragma unroll
    for (int k = t; k < PNUM; k += 128) {
        __half2 gh = __float22half2_rn(gv[k]);
        sg[k]        = gh;
        sg[k + PNUM] = gh;
        __half2 ph = __float22half2_rn(pv[k]);
        sp[0][k]                      = ph;   // sp[s][j] = p[(j+s) % 512]
        sp[1][(k + 511) & 511]        = ph;
        sp[2][(k + 510) & 511]        = ph;
        sp[3][(k + 509) & 511]        = ph;
    }
    __syncthreads();

    const int warp = t >> 5;
    const int lane = t & 31;
    const int r    = warp;                 // shift residue mod 4 handled by this warp
    const int s    = (4 - r) & 3;          // pred rotation so q base is 4-point aligned
    const int A    = h * 256 + r + 8 * lane;   // shift A; shift B = A + 4

    const uint4* qf = reinterpret_cast<const uint4*>(sg) + ((A + s) >> 2);
    const uint4* pf = reinterpret_cast<const uint4*>(sp[s]);

    const __half2 one2 = __floats2half2_rn(1.0f, 1.0f);
    const __half2 nh2  = __floats2half2_rn(-0.5f, -0.5f);
    const __half2 z2   = __floats2half2_rn(0.0f, 0.0f);

    __half2 hA0=z2,hA1=z2,hA2=z2,hA3=z2, hB0=z2,hB1=z2,hB2=z2,hB3=z2;
    float fAx=0.f, fAy=0.f, fBx=0.f, fBy=0.f;

    uint4 Pprev = pf[127];                 // cyclic wrap: B's m=0 terms use j=508..511

    for (int c = 0; c < 16; ++c) {
        #pragma unroll
        for (int mm = 0; mm < 8; ++mm) {
            const int m = c * 8 + mm;
            uint4 P = pf[m];
            uint4 Q = qf[m];
            // shift A: pairs (p[4m+e], g[A+4m+e])
            sl1_h2(P.x, Q.x, one2, nh2, hA0);
            sl1_h2(P.y, Q.y, one2, nh2, hA1);
            sl1_h2(P.z, Q.z, one2, nh2, hA2);
            sl1_h2(P.w, Q.w, one2, nh2, hA3);
            // shift B = A+4: same Q, pred delayed one float4
            sl1_h2(Pprev.x, Q.x, one2, nh2, hB0);
            sl1_h2(Pprev.y, Q.y, one2, nh2, hB1);
            sl1_h2(Pprev.z, Q.z, one2, nh2, hB2);
            sl1_h2(Pprev.w, Q.w, one2, nh2, hB3);
            Pprev = P;
        }
        // drain fp16 chunk accumulators into fp32 (keeps fp16 magnitudes small)
        __half2 cA = __hadd2(__hadd2(hA0, hA1), __hadd2(hA2, hA3));
        __half2 cB = __hadd2(__hadd2(hB0, hB1), __hadd2(hB2, hB3));
        fAx += __low2float(cA);  fAy += __high2float(cA);
        fBx += __low2float(cB);  fBy += __high2float(cB);
        hA0=z2;hA1=z2;hA2=z2;hA3=z2; hB0=z2;hB1=z2;hB2=z2;hB3=z2;
    }

    float v = fminf(fAx + fAy, fBx + fBy);   // min over this thread's two shifts

    #pragma unroll
    for (int o = 16; o; o >>= 1)
        v = fminf(v, __shfl_xor_sync(0xffffffffu, v, o));
    if (lane == 0) wm[warp] = v;
    __syncthreads();
    if (t == 0)
        g_part[bid] = fminf(fminf(wm[0], wm[1]), fminf(wm[2], wm[3]));
}

__global__ void finish_kernel(float* __restrict__ out) {
    __shared__ float wm[16];
    const int t = threadIdx.x;   // 512 threads: one per lb
    float v = fminf(g_part[t], g_part[t + NLB]);   // min over the two halves
    #pragma unroll
    for (int o = 16; o; o >>= 1)
        v += __shfl_xor_sync(0xffffffffu, v, o);
    if ((t & 31) == 0) wm[t >> 5] = v;
    __syncthreads();
    if (t < 16) {
        v = wm[t];
        #pragma unroll
        for (int o = 8; o; o >>= 1)
            v += __shfl_xor_sync(0x0000ffffu, v, o);
        if (t == 0)
            *out = v * (1.0f / ((float)PNUM * BATCH * LPREDS));
    }
}

extern "C" void kernel_launch(void* const* d_in, const int* in_sizes, int n_in,
                              void* d_out, int out_size) {
    const float* pred = (const float*)d_in[0];   // (L, B, P, 2) fp32
    const float* gt   = (const float*)d_in[1];   // (B, P, 2) fp32
    float* out = (float*)d_out;

    poly_main<<<2 * NLB, 128>>>(pred, gt);
    finish_kernel<<<1, NLB>>>(out);
}